// round 15
// baseline (speedup 1.0000x reference)
#include <cuda_runtime.h>
#include <cuda_fp16.h>
#include <cstdint>
#include <cstddef>

// Shapes: B=256, N=50 -> PAIRS=12800; KADJ=12; D=128
#define PAIRS   12800
#define D_      128
#define KADJ    12
#define PPT     10            // pairs per tile (120 rows + 8 pad = 128)
#define TILES1  (PAIRS / PPT) // 1280
#define GRID1   148           // persistent CTAs
#define NTHR    512           // 16 warps: warps 0-7 nt[0,8), warps 8-15 nt[8,16)
#define RSF     136           // padded row stride in floats (544 B) -> conflict-free LDS
#define RSB     544           // padded row stride in bytes

// ------------------------------------------------------------------ scratch
__device__ float g_att[(size_t)PAIRS * D_];

// ------------------------------------------------------------------ helpers
__device__ __forceinline__ uint32_t h2(float v0, float v1) {
    __half2 h = __floats2half2_rn(v0, v1);
    uint32_t u; memcpy(&u, &h, 4); return u;
}
__device__ __forceinline__ void mma_fp16(float* c, uint4 a, uint32_t b0, uint32_t b1) {
    asm volatile(
        "mma.sync.aligned.m16n8k16.row.col.f32.f16.f16.f32 "
        "{%0,%1,%2,%3}, {%4,%5,%6,%7}, {%8,%9}, {%0,%1,%2,%3};\n"
        : "+f"(c[0]), "+f"(c[1]), "+f"(c[2]), "+f"(c[3])
        : "r"(a.x), "r"(a.y), "r"(a.z), "r"(a.w), "r"(b0), "r"(b1));
}
__device__ __forceinline__ uint32_t smem_u32(const void* p) {
    uint32_t a;
    asm("{ .reg .u64 t; cvta.to.shared.u64 t, %1; cvt.u32.u64 %0, t; }" : "=r"(a) : "l"(p));
    return a;
}
#define CP16(dst_u32, src_ptr) \
    asm volatile("cp.async.cg.shared.global [%0], [%1], 16;" :: "r"(dst_u32), "l"(src_ptr))
#define CP_COMMIT() asm volatile("cp.async.commit_group;" ::: "memory")
#define CP_WAIT0()  asm volatile("cp.async.wait_group 0;" ::: "memory")

// In-kernel B-fragment build (hi-only): coalesced gmem reads, scatter STS
// into m16n8k16 B-frag order.
__device__ __forceinline__ void build_B_frags(uint32_t* sBw, const float* __restrict__ w,
                                              int kpairs, int tid) {
    const int words = kpairs * 128;
    for (int i = tid; i < words; i += NTHR) {
        const int q = i >> 7, n = i & 127;
        const float a = w[(2 * q) * 128 + n];
        const float b = w[(2 * q + 1) * 128 + n];
        const int ks = q >> 3, rem = q & 7, r = rem >> 2, l2 = rem & 3;
        const int nt = n >> 3, ln = (n & 7) * 4 + l2;
        sBw[(((ks * 16 + nt) * 32 + ln) << 1) | r] = h2(a, b);
    }
}

// -------------------------------------------------------- kernel1 (attention)
// smem byte offsets (double-buffered raw tiles, 544B padded rows)
#define K1_A     0        // 32768 : A frags fp16 [ks8][mt8][lane][uint4]
#define K1_B     32768    // 32768 : w1 B frags HI only, uint2 [ks8][nt16][lane]
#define K1_ADJ0  65536    // 65280
#define K1_ADJ1  130816   // 65280
#define K1_AVE0  196096   // 5440
#define K1_AVE1  201536   // 5440
#define K1_WGT0  206976   // 512
#define K1_WGT1  207488   // 512
#define K1_W1L   208000   // 512
#define K1_W2    208512   // 512
#define K1_LOG   209024   // 1024 : two partial banks [2][128]
#define K1_ALP   210048   // 512
#define K1_SIZE  210560

__device__ __forceinline__ void k1_prefetch(uint32_t sbase, uint32_t oadj, uint32_t oave,
                                            uint32_t owgt, const float* adj_g,
                                            const float* ave_g, const float* wgt_g,
                                            int tile, int tid) {
    const char* adjp = (const char*)(adj_g + (size_t)tile * PPT * KADJ * D_);
    const char* avep = (const char*)(ave_g + (size_t)tile * PPT * D_);
    const char* wgtp = (const char*)(wgt_g + (size_t)tile * PPT * KADJ);
    for (int i = tid; i < 3840; i += NTHR)
        CP16(sbase + oadj + (i >> 5) * RSB + (i & 31) * 16, adjp + i * 16);
    for (int i = tid; i < 320; i += NTHR)
        CP16(sbase + oave + (i >> 5) * RSB + (i & 31) * 16, avep + i * 16);
    if (tid < 30) CP16(sbase + owgt + tid * 16, wgtp + tid * 16);
}

__global__ void __launch_bounds__(NTHR, 1) kernel1(
    const float* __restrict__ ave_g, const float* __restrict__ adj_g,
    const float* __restrict__ wgt_g, const float* __restrict__ w1_g,
    const float* __restrict__ w2_g) {
    extern __shared__ __align__(16) unsigned char sm[];
    const int tid = threadIdx.x, warp = tid >> 5, lane = tid & 31;
    const int mt8 = warp & 7, grp = warp >> 3, ntb = grp * 8;
    const uint32_t sbase = smem_u32(sm);

    uint4* sA4 = (uint4*)(sm + K1_A);
    uint2* sB2 = (uint2*)(sm + K1_B);
    float* s_w1l = (float*)(sm + K1_W1L);
    float* s_w2  = (float*)(sm + K1_W2);
    float* s_log = (float*)(sm + K1_LOG);   // [2][128]
    float* s_alp = (float*)(sm + K1_ALP);

    // ---- prefetch first tile; build w1 B frags under it ----
    const int tile0 = blockIdx.x;
    k1_prefetch(sbase, K1_ADJ0, K1_AVE0, K1_WGT0, adj_g, ave_g, wgt_g, tile0, tid);
    CP_COMMIT();
    build_B_frags((uint32_t*)sB2, w1_g, 64, tid);
    if (tid < 128) { s_w2[tid] = w2_g[tid]; s_w1l[tid] = w1_g[128 * 128 + tid]; }

    // per-lane constants (C-frag row map)
    const int m_lo = mt8 * 16 + (lane >> 2), m_hi = m_lo + 8;
    const int p_lo = m_lo / 12, kk_lo = m_lo - p_lo * 12;
    const int p_hi = m_hi / 12, kk_hi = m_hi - p_hi * 12;
    const bool v_lo = m_lo < PPT * KADJ, v_hi = m_hi < PPT * KADJ;

    int it = 0;
    for (int tile = tile0; tile < TILES1; tile += GRID1, it++) {
        const int cur = it & 1;
        float* s_adj = (float*)(sm + (cur ? K1_ADJ1 : K1_ADJ0));
        float* s_ave = (float*)(sm + (cur ? K1_AVE1 : K1_AVE0));
        float* s_wgt = (float*)(sm + (cur ? K1_WGT1 : K1_WGT0));

        CP_WAIT0();
        __syncthreads();   // current buffers landed everywhere; prev tile fully consumed

        // ---- build A = pre fragments (single fp16), frag f=[ks][mt][lane] ----
        for (int f = tid; f < 2048; f += NTHR) {
            const int ln = f & 31, mt = (f >> 5) & 7, ks = f >> 8;
            const int ma = mt * 16 + (ln >> 2), mb = ma + 8;
            const int k0 = ks * 16 + (ln & 3) * 2, k8 = k0 + 8;
            const int pa = ma / 12; const bool va = ma < 120;
            const int pb = mb / 12; const bool vb = mb < 120;
            float2 z = make_float2(0.f, 0.f);
            float2 aa0 = va ? *(const float2*)(s_ave + pa * RSF + k0) : z;
            float2 aa8 = va ? *(const float2*)(s_ave + pa * RSF + k8) : z;
            float2 ab0 = vb ? *(const float2*)(s_ave + pb * RSF + k0) : z;
            float2 ab8 = vb ? *(const float2*)(s_ave + pb * RSF + k8) : z;
            float2 da0 = va ? *(const float2*)(s_adj + ma * RSF + k0) : z;
            float2 da8 = va ? *(const float2*)(s_adj + ma * RSF + k8) : z;
            float2 db0 = vb ? *(const float2*)(s_adj + mb * RSF + k0) : z;
            float2 db8 = vb ? *(const float2*)(s_adj + mb * RSF + k8) : z;
            uint4 H;
            H.x = h2(aa0.x * da0.x, aa0.y * da0.y);
            H.y = h2(ab0.x * db0.x, ab0.y * db0.y);
            H.z = h2(aa8.x * da8.x, aa8.y * da8.y);
            H.w = h2(ab8.x * db8.x, ab8.y * db8.y);
            sA4[f] = H;
        }
        __syncthreads();   // A ready

        // ---- prefetch next tile into the other buffer (hidden under mma) ----
        {
            const int nxt = tile + GRID1;
            if (nxt < TILES1)
                k1_prefetch(sbase, cur ? K1_ADJ0 : K1_ADJ1, cur ? K1_AVE0 : K1_AVE1,
                            cur ? K1_WGT0 : K1_WGT1, adj_g, ave_g, wgt_g, nxt, tid);
            CP_COMMIT();
        }

        // ---- GEMM1: 8 n-tiles per warp (2 warp-groups), hi-product only ----
        float acc[8][4];
        #pragma unroll
        for (int j = 0; j < 8; j++)
            #pragma unroll
            for (int q = 0; q < 4; q++) acc[j][q] = 0.f;
        #pragma unroll
        for (int ks = 0; ks < 8; ks++) {
            const uint4 A = sA4[(ks * 8 + mt8) * 32 + lane];
            #pragma unroll
            for (int j = 0; j < 8; j++) {
                const uint2 B = sB2[((ks * 16 + ntb + j) * 32 + lane) * 1];
                mma_fp16(acc[j], A, B.x, B.y);
            }
        }
        // ---- epilogue: rank-1 wgt correction + leaky + w2 dot (per group) ----
        const float wv_lo = v_lo ? s_wgt[p_lo * KADJ + kk_lo] : 0.f;
        const float wv_hi = v_hi ? s_wgt[p_hi * KADJ + kk_hi] : 0.f;
        float part0 = 0.f, part1 = 0.f;
        #pragma unroll
        for (int j = 0; j < 8; j++) {
            #pragma unroll
            for (int jj = 0; jj < 2; jj++) {
                const int c = (ntb + j) * 8 + (lane & 3) * 2 + jj;
                const float w1lc = s_w1l[c], w2c = s_w2[c];
                float a = fmaf(wv_lo, w1lc, acc[j][jj]);
                part0 = fmaf(fmaxf(a, 0.2f * a), w2c, part0);
                float b = fmaf(wv_hi, w1lc, acc[j][2 + jj]);
                part1 = fmaf(fmaxf(b, 0.2f * b), w2c, part1);
            }
        }
        part0 += __shfl_xor_sync(0xffffffffu, part0, 1);
        part0 += __shfl_xor_sync(0xffffffffu, part0, 2);
        part1 += __shfl_xor_sync(0xffffffffu, part1, 1);
        part1 += __shfl_xor_sync(0xffffffffu, part1, 2);
        if ((lane & 3) == 0) {
            s_log[grp * 128 + m_lo] = part0;
            s_log[grp * 128 + m_hi] = part1;
        }
        __syncthreads();
        // ---- softmax per pair (serial, 10 threads, deterministic) ----
        if (tid < PPT) {
            float lg[KADJ];
            #pragma unroll
            for (int k = 0; k < KADJ; k++) {
                const int m = tid * KADJ + k;
                lg[k] = s_log[m] + s_log[128 + m];
            }
            float mx = lg[0];
            #pragma unroll
            for (int k = 1; k < KADJ; k++) mx = fmaxf(mx, lg[k]);
            float e[KADJ], ssum = 0.f;
            #pragma unroll
            for (int k = 0; k < KADJ; k++) { e[k] = __expf(lg[k] - mx); ssum += e[k]; }
            const float inv = 1.f / ssum;
            #pragma unroll
            for (int k = 0; k < KADJ; k++) s_alp[tid * KADJ + k] = e[k] * inv;
        }
        __syncthreads();
        // ---- att = sum_k alpha * adj (fp32 exact) ----
        const size_t pbase = (size_t)tile * PPT;
        #pragma unroll
        for (int i = tid; i < PPT * D_; i += NTHR) {
            const int p = i >> 7, d = i & 127;
            const float* adp = s_adj + (p * KADJ) * RSF + d;
            float a = 0.f;
            #pragma unroll
            for (int k = 0; k < KADJ; k++) a = fmaf(s_alp[p * KADJ + k], adp[k * RSF], a);
            g_att[(pbase + p) * D_ + d] = a;
        }
    }
}

// -------------------------------------------------------- kernel2 (w3 + relu)
#define K2_B    0         // 65536 : w3 B frags HI only, uint2 [ks16][nt16][lane]
#define K2_A    65536     // 32768 : A frags fp16 [ks8][mt8][lane][uint4]
#define K2_RAW  98304     // 69632 : raw rows, padded stride
#define K2_SIZE 167936

__global__ void __launch_bounds__(NTHR, 1) kernel2(const float* __restrict__ itm,
                                                   const float* __restrict__ w3_g,
                                                   float* __restrict__ out) {
    extern __shared__ __align__(16) unsigned char sm[];
    const int tid = threadIdx.x, warp = tid >> 5, lane = tid & 31;
    const int mt8 = warp & 7, ntb = (warp >> 3) * 8;
    const uint32_t sbase = smem_u32(sm);
    uint2* sB2 = (uint2*)(sm + K2_B);
    uint4* sA4 = (uint4*)(sm + K2_A);
    float* s_raw = (float*)(sm + K2_RAW);

    const size_t rowbase = (size_t)blockIdx.x * 128;

    // 1. prefetch itm rows (raw, padded) ; 2. build w3 B frags under it
    {
        const char* p = (const char*)(itm + rowbase * D_);
        for (int i = tid; i < 4096; i += NTHR)
            CP16(sbase + K2_RAW + (i >> 5) * RSB + (i & 31) * 16, p + i * 16);
        CP_COMMIT();
    }
    build_B_frags((uint32_t*)sB2, w3_g, 128, tid);

    float acc[8][4];
    #pragma unroll
    for (int j = 0; j < 8; j++)
        #pragma unroll
        for (int q = 0; q < 4; q++) acc[j][q] = 0.f;

    #pragma unroll
    for (int half = 0; half < 2; half++) {
        CP_WAIT0();
        __syncthreads();   // raw rows landed; B frags (half 0) / A reads (half 1) done
        // ---- build A frags from smem raw (conflict-free, padded stride) ----
        for (int f = tid; f < 2048; f += NTHR) {
            const int ln = f & 31, mt = (f >> 5) & 7, ks = f >> 8;
            const int ra = mt * 16 + (ln >> 2), rb = ra + 8;
            const int k0 = ks * 16 + (ln & 3) * 2, k8 = k0 + 8;
            float2 fa0 = *(const float2*)(s_raw + ra * RSF + k0);
            float2 fb0 = *(const float2*)(s_raw + rb * RSF + k0);
            float2 fa8 = *(const float2*)(s_raw + ra * RSF + k8);
            float2 fb8 = *(const float2*)(s_raw + rb * RSF + k8);
            uint4 H;
            H.x = h2(fa0.x, fa0.y);
            H.y = h2(fb0.x, fb0.y);
            H.z = h2(fa8.x, fa8.y);
            H.w = h2(fb8.x, fb8.y);
            sA4[f] = H;
        }
        __syncthreads();   // A ready; raw buffer free for overwrite
        // ---- prefetch att rows into raw (hidden under half-0 mma) ----
        if (half == 0) {
            const char* p = (const char*)((const float*)g_att + rowbase * D_);
            for (int i = tid; i < 4096; i += NTHR)
                CP16(sbase + K2_RAW + (i >> 5) * RSB + (i & 31) * 16, p + i * 16);
            CP_COMMIT();
        }
        // ---- mma: hi-product only, 8 nt per warp ----
        #pragma unroll
        for (int ks = 0; ks < 8; ks++) {
            const int gks = half * 8 + ks;
            const uint4 A = sA4[(ks * 8 + mt8) * 32 + lane];
            #pragma unroll
            for (int j = 0; j < 8; j++) {
                const uint2 B = sB2[(gks * 16 + ntb + j) * 32 + lane];
                mma_fp16(acc[j], A, B.x, B.y);
            }
        }
    }
    // relu + store (each warp owns rows [mt8*16,+16) x cols [ntb*8,+64) — no overlap)
    const size_t r_lo = rowbase + mt8 * 16 + (lane >> 2), r_hi = r_lo + 8;
    #pragma unroll
    for (int j = 0; j < 8; j++) {
        const int c = (ntb + j) * 8 + (lane & 3) * 2;
        *(float2*)(out + r_lo * D_ + c) =
            make_float2(fmaxf(acc[j][0], 0.f), fmaxf(acc[j][1], 0.f));
        *(float2*)(out + r_hi * D_ + c) =
            make_float2(fmaxf(acc[j][2], 0.f), fmaxf(acc[j][3], 0.f));
    }
}

// ------------------------------------------------------------------ launch
extern "C" void kernel_launch(void* const* d_in, const int* in_sizes, int n_in,
                              void* d_out, int out_size) {
    const float *itm = nullptr, *ave = nullptr, *adj = nullptr, *wgt = nullptr;
    const float *w1 = nullptr, *w2 = nullptr, *w3 = nullptr;
    for (int i = 0; i < n_in; i++) {
        const float* p = (const float*)d_in[i];
        switch (in_sizes[i]) {
            case 1638400:  if (!itm) itm = p; else ave = p; break;  // itm first, then ave
            case 19660800: adj = p; break;
            case 153600:   wgt = p; break;
            case 16512:    w1 = p; break;
            case 128:      w2 = p; break;
            case 32768:    w3 = p; break;
            default: break;
        }
    }
    cudaFuncSetAttribute(kernel1, cudaFuncAttributeMaxDynamicSharedMemorySize, K1_SIZE);
    cudaFuncSetAttribute(kernel2, cudaFuncAttributeMaxDynamicSharedMemorySize, K2_SIZE);

    kernel1<<<GRID1, NTHR, K1_SIZE>>>(ave, adj, wgt, w1, w2);
    kernel2<<<PAIRS / 128, NTHR, K2_SIZE>>>(itm, w3, (float*)d_out);
}

// round 16
// speedup vs baseline: 1.0714x; 1.0714x over previous
#include <cuda_runtime.h>
#include <cuda_fp16.h>
#include <cstdint>
#include <cstddef>

// Shapes: B=256, N=50 -> PAIRS=12800; KADJ=12; D=128
#define PAIRS   12800
#define D_      128
#define KADJ    12
#define PPT     10            // pairs per tile (120 rows + 8 pad = 128)
#define TILES1  (PAIRS / PPT) // 1280
#define GRID1   148           // persistent CTAs
#define K1_THR  256           // kernel1: 8 warps (measured best, R14)
#define K2_THR  512           // kernel2: 16 warps (measured best, R15)
#define RSF     136           // padded row stride in floats (544 B) -> conflict-free LDS
#define RSB     544           // padded row stride in bytes

// ------------------------------------------------------------------ scratch
__device__ float g_att[(size_t)PAIRS * D_];

// ------------------------------------------------------------------ helpers
__device__ __forceinline__ uint32_t h2(float v0, float v1) {
    __half2 h = __floats2half2_rn(v0, v1);
    uint32_t u; memcpy(&u, &h, 4); return u;
}
__device__ __forceinline__ void mma_fp16(float* c, uint4 a, uint32_t b0, uint32_t b1) {
    asm volatile(
        "mma.sync.aligned.m16n8k16.row.col.f32.f16.f16.f32 "
        "{%0,%1,%2,%3}, {%4,%5,%6,%7}, {%8,%9}, {%0,%1,%2,%3};\n"
        : "+f"(c[0]), "+f"(c[1]), "+f"(c[2]), "+f"(c[3])
        : "r"(a.x), "r"(a.y), "r"(a.z), "r"(a.w), "r"(b0), "r"(b1));
}
__device__ __forceinline__ uint32_t smem_u32(const void* p) {
    uint32_t a;
    asm("{ .reg .u64 t; cvta.to.shared.u64 t, %1; cvt.u32.u64 %0, t; }" : "=r"(a) : "l"(p));
    return a;
}
#define CP16(dst_u32, src_ptr) \
    asm volatile("cp.async.cg.shared.global [%0], [%1], 16;" :: "r"(dst_u32), "l"(src_ptr))
#define CP_COMMIT() asm volatile("cp.async.commit_group;" ::: "memory")
#define CP_WAIT0()  asm volatile("cp.async.wait_group 0;" ::: "memory")

// In-kernel B-fragment build (hi-only): coalesced gmem reads, scatter STS
// into m16n8k16 B-frag order.
__device__ __forceinline__ void build_B_frags(uint32_t* sBw, const float* __restrict__ w,
                                              int kpairs, int tid, int nthr) {
    const int words = kpairs * 128;
    for (int i = tid; i < words; i += nthr) {
        const int q = i >> 7, n = i & 127;
        const float a = w[(2 * q) * 128 + n];
        const float b = w[(2 * q + 1) * 128 + n];
        const int ks = q >> 3, rem = q & 7, r = rem >> 2, l2 = rem & 3;
        const int nt = n >> 3, ln = (n & 7) * 4 + l2;
        sBw[(((ks * 16 + nt) * 32 + ln) << 1) | r] = h2(a, b);
    }
}

// -------------------------------------------------------- kernel1 (attention)
// 256 threads (8 warps; warp = m-tile, 16 n-tiles each). Double-buffered raw tiles.
#define K1_A     0        // 32768 : A frags fp16 [ks8][mt8][lane][uint4]
#define K1_B     32768    // 32768 : w1 B frags HI only, uint2 [ks8][nt16][lane]
#define K1_ADJ0  65536    // 65280
#define K1_ADJ1  130816   // 65280
#define K1_AVE0  196096   // 5440
#define K1_AVE1  201536   // 5440
#define K1_WGT0  206976   // 512
#define K1_WGT1  207488   // 512
#define K1_W1L   208000   // 512
#define K1_W2    208512   // 512
#define K1_LOG   209024   // 512
#define K1_ALP   209536   // 512
#define K1_SIZE  210048

__device__ __forceinline__ void k1_prefetch(uint32_t sbase, uint32_t oadj, uint32_t oave,
                                            uint32_t owgt, const float* adj_g,
                                            const float* ave_g, const float* wgt_g,
                                            int tile, int tid) {
    const char* adjp = (const char*)(adj_g + (size_t)tile * PPT * KADJ * D_);
    const char* avep = (const char*)(ave_g + (size_t)tile * PPT * D_);
    const char* wgtp = (const char*)(wgt_g + (size_t)tile * PPT * KADJ);
    for (int i = tid; i < 3840; i += K1_THR)
        CP16(sbase + oadj + (i >> 5) * RSB + (i & 31) * 16, adjp + i * 16);
    for (int i = tid; i < 320; i += K1_THR)
        CP16(sbase + oave + (i >> 5) * RSB + (i & 31) * 16, avep + i * 16);
    if (tid < 30) CP16(sbase + owgt + tid * 16, wgtp + tid * 16);
}

__global__ void __launch_bounds__(K1_THR, 1) kernel1(
    const float* __restrict__ ave_g, const float* __restrict__ adj_g,
    const float* __restrict__ wgt_g, const float* __restrict__ w1_g,
    const float* __restrict__ w2_g) {
    extern __shared__ __align__(16) unsigned char sm[];
    const int tid = threadIdx.x, warp = tid >> 5, lane = tid & 31;
    const uint32_t sbase = smem_u32(sm);

    uint4* sA4 = (uint4*)(sm + K1_A);
    uint2* sB2 = (uint2*)(sm + K1_B);
    float* s_w1l = (float*)(sm + K1_W1L);
    float* s_w2  = (float*)(sm + K1_W2);
    float* s_log = (float*)(sm + K1_LOG);
    float* s_alp = (float*)(sm + K1_ALP);

    // ---- prefetch first tile; build w1 B frags under it ----
    const int tile0 = blockIdx.x;
    k1_prefetch(sbase, K1_ADJ0, K1_AVE0, K1_WGT0, adj_g, ave_g, wgt_g, tile0, tid);
    CP_COMMIT();
    build_B_frags((uint32_t*)sB2, w1_g, 64, tid, K1_THR);
    if (tid < 128) { s_w2[tid] = w2_g[tid]; s_w1l[tid] = w1_g[128 * 128 + tid]; }

    // per-lane constants (C-frag row map)
    const int m_lo = warp * 16 + (lane >> 2), m_hi = m_lo + 8;
    const int p_lo = m_lo / 12, kk_lo = m_lo - p_lo * 12;
    const int p_hi = m_hi / 12, kk_hi = m_hi - p_hi * 12;
    const bool v_lo = m_lo < PPT * KADJ, v_hi = m_hi < PPT * KADJ;

    int it = 0;
    for (int tile = tile0; tile < TILES1; tile += GRID1, it++) {
        const int cur = it & 1;
        float* s_adj = (float*)(sm + (cur ? K1_ADJ1 : K1_ADJ0));
        float* s_ave = (float*)(sm + (cur ? K1_AVE1 : K1_AVE0));
        float* s_wgt = (float*)(sm + (cur ? K1_WGT1 : K1_WGT0));

        CP_WAIT0();
        __syncthreads();   // current buffers landed everywhere; prev tile fully consumed

        // ---- build A = pre fragments (single fp16), frag f=[ks][mt][lane] ----
        for (int f = tid; f < 2048; f += K1_THR) {
            const int ln = f & 31, mt = (f >> 5) & 7, ks = f >> 8;
            const int ma = mt * 16 + (ln >> 2), mb = ma + 8;
            const int k0 = ks * 16 + (ln & 3) * 2, k8 = k0 + 8;
            const int pa = ma / 12; const bool va = ma < 120;
            const int pb = mb / 12; const bool vb = mb < 120;
            float2 z = make_float2(0.f, 0.f);
            float2 aa0 = va ? *(const float2*)(s_ave + pa * RSF + k0) : z;
            float2 aa8 = va ? *(const float2*)(s_ave + pa * RSF + k8) : z;
            float2 ab0 = vb ? *(const float2*)(s_ave + pb * RSF + k0) : z;
            float2 ab8 = vb ? *(const float2*)(s_ave + pb * RSF + k8) : z;
            float2 da0 = va ? *(const float2*)(s_adj + ma * RSF + k0) : z;  // adj row == ma
            float2 da8 = va ? *(const float2*)(s_adj + ma * RSF + k8) : z;
            float2 db0 = vb ? *(const float2*)(s_adj + mb * RSF + k0) : z;
            float2 db8 = vb ? *(const float2*)(s_adj + mb * RSF + k8) : z;
            uint4 H;
            H.x = h2(aa0.x * da0.x, aa0.y * da0.y);
            H.y = h2(ab0.x * db0.x, ab0.y * db0.y);
            H.z = h2(aa8.x * da8.x, aa8.y * da8.y);
            H.w = h2(ab8.x * db8.x, ab8.y * db8.y);
            sA4[f] = H;
        }
        __syncthreads();   // A ready

        // ---- prefetch next tile into the other buffer (hidden under mma) ----
        {
            const int nxt = tile + GRID1;
            if (nxt < TILES1)
                k1_prefetch(sbase, cur ? K1_ADJ0 : K1_ADJ1, cur ? K1_AVE0 : K1_AVE1,
                            cur ? K1_WGT0 : K1_WGT1, adj_g, ave_g, wgt_g, nxt, tid);
            CP_COMMIT();
        }

        // ---- GEMM1: 16 independent n-tiles per warp, hi-product only ----
        float acc[16][4];
        #pragma unroll
        for (int nt = 0; nt < 16; nt++)
            #pragma unroll
            for (int q = 0; q < 4; q++) acc[nt][q] = 0.f;
        #pragma unroll
        for (int ks = 0; ks < 8; ks++) {
            const uint4 A = sA4[(ks * 8 + warp) * 32 + lane];
            #pragma unroll
            for (int nt = 0; nt < 16; nt++) {
                const uint2 B = sB2[(ks * 16 + nt) * 32 + lane];
                mma_fp16(acc[nt], A, B.x, B.y);
            }
        }
        // ---- epilogue: rank-1 wgt correction + leaky + w2 dot ----
        const float wv_lo = v_lo ? s_wgt[p_lo * KADJ + kk_lo] : 0.f;
        const float wv_hi = v_hi ? s_wgt[p_hi * KADJ + kk_hi] : 0.f;
        float part0 = 0.f, part1 = 0.f;
        #pragma unroll
        for (int nt = 0; nt < 16; nt++) {
            #pragma unroll
            for (int j = 0; j < 2; j++) {
                const int c = nt * 8 + (lane & 3) * 2 + j;
                const float w1lc = s_w1l[c], w2c = s_w2[c];
                float a = fmaf(wv_lo, w1lc, acc[nt][j]);
                part0 = fmaf(fmaxf(a, 0.2f * a), w2c, part0);
                float b = fmaf(wv_hi, w1lc, acc[nt][2 + j]);
                part1 = fmaf(fmaxf(b, 0.2f * b), w2c, part1);
            }
        }
        part0 += __shfl_xor_sync(0xffffffffu, part0, 1);
        part0 += __shfl_xor_sync(0xffffffffu, part0, 2);
        part1 += __shfl_xor_sync(0xffffffffu, part1, 1);
        part1 += __shfl_xor_sync(0xffffffffu, part1, 2);
        if ((lane & 3) == 0) { s_log[m_lo] = part0; s_log[m_hi] = part1; }
        __syncthreads();
        // ---- softmax per pair (serial, 10 threads, deterministic) ----
        if (tid < PPT) {
            const float* lg = s_log + tid * KADJ;
            float mx = lg[0];
            #pragma unroll
            for (int k = 1; k < KADJ; k++) mx = fmaxf(mx, lg[k]);
            float e[KADJ], ssum = 0.f;
            #pragma unroll
            for (int k = 0; k < KADJ; k++) { e[k] = __expf(lg[k] - mx); ssum += e[k]; }
            const float inv = 1.f / ssum;
            #pragma unroll
            for (int k = 0; k < KADJ; k++) s_alp[tid * KADJ + k] = e[k] * inv;
        }
        __syncthreads();
        // ---- att = sum_k alpha * adj (fp32 exact) ----
        const size_t pbase = (size_t)tile * PPT;
        #pragma unroll
        for (int i = tid; i < PPT * D_; i += K1_THR) {
            const int p = i >> 7, d = i & 127;
            const float* adp = s_adj + (p * KADJ) * RSF + d;
            float a = 0.f;
            #pragma unroll
            for (int k = 0; k < KADJ; k++) a = fmaf(s_alp[p * KADJ + k], adp[k * RSF], a);
            g_att[(pbase + p) * D_ + d] = a;
        }
    }
}

// -------------------------------------------------------- kernel2 (w3 + relu)
// 512 threads (16 warps; warps 0-7 nt[0,8), warps 8-15 nt[8,16))
#define K2_B    0         // 65536 : w3 B frags HI only, uint2 [ks16][nt16][lane]
#define K2_A    65536     // 32768 : A frags fp16 [ks8][mt8][lane][uint4]
#define K2_RAW  98304     // 69632 : raw rows, padded stride
#define K2_SIZE 167936

__global__ void __launch_bounds__(K2_THR, 1) kernel2(const float* __restrict__ itm,
                                                     const float* __restrict__ w3_g,
                                                     float* __restrict__ out) {
    extern __shared__ __align__(16) unsigned char sm[];
    const int tid = threadIdx.x, warp = tid >> 5, lane = tid & 31;
    const int mt8 = warp & 7, ntb = (warp >> 3) * 8;
    const uint32_t sbase = smem_u32(sm);
    uint2* sB2 = (uint2*)(sm + K2_B);
    uint4* sA4 = (uint4*)(sm + K2_A);
    float* s_raw = (float*)(sm + K2_RAW);

    const size_t rowbase = (size_t)blockIdx.x * 128;

    // 1. prefetch itm rows (raw, padded) ; 2. build w3 B frags under it
    {
        const char* p = (const char*)(itm + rowbase * D_);
        for (int i = tid; i < 4096; i += K2_THR)
            CP16(sbase + K2_RAW + (i >> 5) * RSB + (i & 31) * 16, p + i * 16);
        CP_COMMIT();
    }
    build_B_frags((uint32_t*)sB2, w3_g, 128, tid, K2_THR);

    float acc[8][4];
    #pragma unroll
    for (int j = 0; j < 8; j++)
        #pragma unroll
        for (int q = 0; q < 4; q++) acc[j][q] = 0.f;

    #pragma unroll
    for (int half = 0; half < 2; half++) {
        CP_WAIT0();
        __syncthreads();   // raw rows landed; B frags (half 0) / A reads (half 1) done
        // ---- build A frags from smem raw (conflict-free, padded stride) ----
        for (int f = tid; f < 2048; f += K2_THR) {
            const int ln = f & 31, mt = (f >> 5) & 7, ks = f >> 8;
            const int ra = mt * 16 + (ln >> 2), rb = ra + 8;
            const int k0 = ks * 16 + (ln & 3) * 2, k8 = k0 + 8;
            float2 fa0 = *(const float2*)(s_raw + ra * RSF + k0);
            float2 fb0 = *(const float2*)(s_raw + rb * RSF + k0);
            float2 fa8 = *(const float2*)(s_raw + ra * RSF + k8);
            float2 fb8 = *(const float2*)(s_raw + rb * RSF + k8);
            uint4 H;
            H.x = h2(fa0.x, fa0.y);
            H.y = h2(fb0.x, fb0.y);
            H.z = h2(fa8.x, fa8.y);
            H.w = h2(fb8.x, fb8.y);
            sA4[f] = H;
        }
        __syncthreads();   // A ready; raw buffer free for overwrite
        // ---- prefetch att rows into raw (hidden under half-0 mma) ----
        if (half == 0) {
            const char* p = (const char*)((const float*)g_att + rowbase * D_);
            for (int i = tid; i < 4096; i += K2_THR)
                CP16(sbase + K2_RAW + (i >> 5) * RSB + (i & 31) * 16, p + i * 16);
            CP_COMMIT();
        }
        // ---- mma: hi-product only, 8 nt per warp ----
        #pragma unroll
        for (int ks = 0; ks < 8; ks++) {
            const int gks = half * 8 + ks;
            const uint4 A = sA4[(ks * 8 + mt8) * 32 + lane];
            #pragma unroll
            for (int j = 0; j < 8; j++) {
                const uint2 B = sB2[(gks * 16 + ntb + j) * 32 + lane];
                mma_fp16(acc[j], A, B.x, B.y);
            }
        }
    }
    // relu + store (each warp owns rows [mt8*16,+16) x cols [ntb*8,+64) — no overlap)
    const size_t r_lo = rowbase + mt8 * 16 + (lane >> 2), r_hi = r_lo + 8;
    #pragma unroll
    for (int j = 0; j < 8; j++) {
        const int c = (ntb + j) * 8 + (lane & 3) * 2;
        *(float2*)(out + r_lo * D_ + c) =
            make_float2(fmaxf(acc[j][0], 0.f), fmaxf(acc[j][1], 0.f));
        *(float2*)(out + r_hi * D_ + c) =
            make_float2(fmaxf(acc[j][2], 0.f), fmaxf(acc[j][3], 0.f));
    }
}

// ------------------------------------------------------------------ launch
extern "C" void kernel_launch(void* const* d_in, const int* in_sizes, int n_in,
                              void* d_out, int out_size) {
    const float *itm = nullptr, *ave = nullptr, *adj = nullptr, *wgt = nullptr;
    const float *w1 = nullptr, *w2 = nullptr, *w3 = nullptr;
    for (int i = 0; i < n_in; i++) {
        const float* p = (const float*)d_in[i];
        switch (in_sizes[i]) {
            case 1638400:  if (!itm) itm = p; else ave = p; break;  // itm first, then ave
            case 19660800: adj = p; break;
            case 153600:   wgt = p; break;
            case 16512:    w1 = p; break;
            case 128:      w2 = p; break;
            case 32768:    w3 = p; break;
            default: break;
        }
    }
    cudaFuncSetAttribute(kernel1, cudaFuncAttributeMaxDynamicSharedMemorySize, K1_SIZE);
    cudaFuncSetAttribute(kernel2, cudaFuncAttributeMaxDynamicSharedMemorySize, K2_SIZE);

    kernel1<<<GRID1, K1_THR, K1_SIZE>>>(ave, adj, wgt, w1, w2);
    kernel2<<<PAIRS / 128, K2_THR, K2_SIZE>>>(itm, w3, (float*)d_out);
}